// round 15
// baseline (speedup 1.0000x reference)
#include <cuda_runtime.h>
#include <cstdint>

typedef unsigned long long ull;

#define C_DIM 32
#define B_DIM 16
#define N_DIM 1024
#define I_DIM 64
#define O_DIM 32
#define CB    (C_DIM * B_DIM)

// 64 MB scratch for priors (C,B,N,O) fp32
__device__ __align__(256) float g_priors[(size_t)C_DIM * B_DIM * N_DIM * O_DIM];

__device__ __forceinline__ ull pack2(float a, float b) {
    ull r; asm("mov.b64 %0, {%1,%2};" : "=l"(r) : "f"(a), "f"(b)); return r;
}
__device__ __forceinline__ void fma2(ull& d, ull a, ull b) {
    asm("fma.rn.f32x2 %0, %1, %2, %0;" : "+l"(d) : "l"(a), "l"(b));
}
__device__ __forceinline__ float2 unpack2(ull v) {
    float lo, hi; asm("mov.b64 {%0,%1}, %2;" : "=f"(lo), "=f"(hi) : "l"(v));
    return make_float2(lo, hi);
}
__device__ __forceinline__ uint32_t smem_u32(const void* p) {
    uint32_t a;
    asm("{ .reg .u64 tmp; cvta.to.shared.u64 tmp, %1; cvt.u32.u64 %0, tmp; }"
        : "=r"(a) : "l"(p));
    return a;
}

// ---------------------------------------------------------------------------
// Kernel 1 (unchanged): priors[c,b,n,o] = sum_i x[b,n,i] * W[c,n,i,o]
// ---------------------------------------------------------------------------
__global__ __launch_bounds__(256, 3) void priors_kernel(
        const float* __restrict__ x, const float* __restrict__ W) {
    __shared__ __align__(16) float sx[8][16][64];   // [n_local][b][i] 32KB

    const int c  = blockIdx.y;
    const int n0 = blockIdx.x * 8;
    const int t  = threadIdx.x;

    const float4* xg  = (const float4*)x;
    float4*       sx4 = (float4*)sx;
#pragma unroll
    for (int k = 0; k < 8; k++) {
        int j  = t + k * 256;            // 0..2047
        int i4 = j & 15;
        int b  = (j >> 4) & 15;
        int nl = j >> 8;
        sx4[(nl * 16 + b) * 16 + i4] = xg[((size_t)b * N_DIM + n0 + nl) * 16 + i4];
    }
    __syncthreads();

    const int nl   = t >> 5;
    const int lane = t & 31;
    const int n    = n0 + nl;

    const float* Wc = W + (((size_t)c * N_DIM + n) * I_DIM) * O_DIM + lane;

    ull acc[16];
#pragma unroll
    for (int b = 0; b < 16; b++) acc[b] = 0ull;

#pragma unroll
    for (int h = 0; h < 4; h++) {
        ull wd[8];
#pragma unroll
        for (int j = 0; j < 8; j++) {
            float w0 = __ldcs(Wc + (h * 16 + 2 * j)     * O_DIM);
            float w1 = __ldcs(Wc + (h * 16 + 2 * j + 1) * O_DIM);
            wd[j] = pack2(w0, w1);
        }
#pragma unroll
        for (int b = 0; b < 16; b++) {
            const ulonglong2* xb = (const ulonglong2*)(&sx[nl][b][h * 16]);
#pragma unroll
            for (int q = 0; q < 4; q++) {
                ulonglong2 xv = xb[q];
                fma2(acc[b], xv.x, wd[2 * q]);
                fma2(acc[b], xv.y, wd[2 * q + 1]);
            }
        }
    }

    float* pout = g_priors + (((size_t)c * B_DIM) * N_DIM + n) * O_DIM + lane;
#pragma unroll
    for (int b = 0; b < 16; b++) {
        float2 f = unpack2(acc[b]);
        pout[(size_t)b * N_DIM * O_DIM] = f.x + f.y;
    }
}

// ---------------------------------------------------------------------------
// Kernel 2: fused routing, one block per (c,b), 512 threads.
// 128KB priors slice staged via cp.async.bulk (UBLKCP — no register
// round-trip, no per-warp MLP cap), then iter-1 sum + iters 2/3 run from
// smem with online softmax. Natural stride 32 floats is conflict-free for
// the 8-lane row-group LDS.128 pattern.
// ---------------------------------------------------------------------------
__global__ __launch_bounds__(512, 1) void routing_fused(float* __restrict__ out) {
    extern __shared__ __align__(128) float sm[];
    float*   P      = sm;                              // 1024*32 = 128KB
    float4*  sred   = (float4*)(P + N_DIM * O_DIM);    // 512 float4 = 8KB
    float*   sm_w   = (float*)(sred + 512);            // 32
    float*   sm_m   = sm_w + 32;                       // 16
    float*   sm_z   = sm_m + 16;                       // 16
    float*   sm_acc = sm_z + 16;                       // 16*32
    ull*     mbar   = (ull*)(sm_acc + 16 * 32);        // 8B (8-aligned)

    const int cb = blockIdx.x;
    const int t  = threadIdx.x;
    const int l  = t & 31;
    const int w  = t >> 5;

    const uint32_t mb  = smem_u32(mbar);
    const uint32_t pP  = smem_u32(P);
    const float*   src = g_priors + (size_t)cb * N_DIM * O_DIM;

    if (t == 0) {
        asm volatile("mbarrier.init.shared.b64 [%0], 1;" :: "r"(mb) : "memory");
    }
    __syncthreads();
    if (t == 0) {
        asm volatile("mbarrier.arrive.expect_tx.shared.b64 _, [%0], %1;"
                     :: "r"(mb), "r"(131072u) : "memory");
        const float* s0 = src;
        const float* s1 = src + 8192;
        const float* s2 = src + 16384;
        const float* s3 = src + 24576;
        asm volatile(
            "cp.async.bulk.shared::cluster.global.mbarrier::complete_tx::bytes "
            "[%0], [%1], %2, [%3];"
            :: "r"(pP), "l"(s0), "r"(32768u), "r"(mb) : "memory");
        asm volatile(
            "cp.async.bulk.shared::cluster.global.mbarrier::complete_tx::bytes "
            "[%0], [%1], %2, [%3];"
            :: "r"(pP + 32768u), "l"(s1), "r"(32768u), "r"(mb) : "memory");
        asm volatile(
            "cp.async.bulk.shared::cluster.global.mbarrier::complete_tx::bytes "
            "[%0], [%1], %2, [%3];"
            :: "r"(pP + 65536u), "l"(s2), "r"(32768u), "r"(mb) : "memory");
        asm volatile(
            "cp.async.bulk.shared::cluster.global.mbarrier::complete_tx::bytes "
            "[%0], [%1], %2, [%3];"
            :: "r"(pP + 98304u), "l"(s3), "r"(32768u), "r"(mb) : "memory");
    }
    // wait for the tile
    {
        uint32_t done;
        asm volatile(
            "{\n\t.reg .pred p;\n\t"
            "mbarrier.try_wait.parity.acquire.cta.shared::cta.b64 p, [%1], 0;\n\t"
            "selp.b32 %0, 1, 0, p;\n\t}"
            : "=r"(done) : "r"(mb) : "memory");
        if (!done) {
            asm volatile(
                "{\n\t.reg .pred P1;\n\t"
                "WL_%=:\n\t"
                "mbarrier.try_wait.parity.acquire.cta.shared::cta.b64 P1, [%0], 0, 0x989680;\n\t"
                "@P1 bra.uni WD_%=;\n\t"
                "bra.uni WL_%=;\n\t"
                "WD_%=:\n\t}"
                :: "r"(mb) : "memory");
        }
    }
    __syncthreads();

    // ---- iter-1 column sums from smem ----
    {
        const int o4   = t & 7;
        const int rowb = t >> 3;         // 0..63
        const float4* P4 = (const float4*)P;
        float4 s = make_float4(0.f, 0.f, 0.f, 0.f);
#pragma unroll
        for (int k = 0; k < 16; k++) {
            float4 p = P4[(rowb + 64 * k) * 8 + o4];
            s.x += p.x; s.y += p.y; s.z += p.z; s.w += p.w;
        }
        sred[t] = s;
    }
    __syncthreads();
    if (t < 32) {
        int oo4 = t >> 2, comp = t & 3;
        float v = 0.f;
#pragma unroll
        for (int g = 0; g < 64; g++)
            v += ((const float*)&sred[oo4 + 8 * g])[comp];
        v *= (1.f / N_DIM);
        float sq = v * v;
#pragma unroll
        for (int off = 16; off; off >>= 1)
            sq += __shfl_xor_sync(~0u, sq, off);
        sm_w[t] = v * (sqrtf(sq) / (1.f + sq));
    }
    __syncthreads();

    // ---- iterations 2 and 3: online softmax from smem ----
    const int sub = l >> 3;     // row within 4-row group
    const int o4  = l & 7;      // float4 within row
    for (int it = 0; it < 2; it++) {
        float4 w4 = *(const float4*)(sm_w + o4 * 4);

        float  m = -3.0e38f, Z = 0.f;
        float4 acc = make_float4(0.f, 0.f, 0.f, 0.f);
#pragma unroll 4
        for (int r = 0; r < 16; r++) {
            int n = r * 64 + w * 4 + sub;
            float4 p = *(const float4*)(P + n * O_DIM + o4 * 4);
            float d = p.x * w4.x + p.y * w4.y + p.z * w4.z + p.w * w4.w;
            d += __shfl_xor_sync(~0u, d, 4);
            d += __shfl_xor_sync(~0u, d, 2);
            d += __shfl_xor_sync(~0u, d, 1);    // 8 row-lanes hold full dot
            float mn = fmaxf(m, d);
            float sc = __expf(m - mn);
            float e  = __expf(d - mn);
            Z = Z * sc + e;
            acc.x = acc.x * sc + e * p.x;
            acc.y = acc.y * sc + e * p.y;
            acc.z = acc.z * sc + e * p.z;
            acc.w = acc.w * sc + e * p.w;
            m = mn;
        }

        // merge the 4 row-subgroups (lanes xor 8, 16)
#pragma unroll
        for (int off = 8; off <= 16; off <<= 1) {
            float m2 = __shfl_xor_sync(~0u, m, off);
            float Z2 = __shfl_xor_sync(~0u, Z, off);
            float ax = __shfl_xor_sync(~0u, acc.x, off);
            float ay = __shfl_xor_sync(~0u, acc.y, off);
            float az = __shfl_xor_sync(~0u, acc.z, off);
            float aw = __shfl_xor_sync(~0u, acc.w, off);
            float M  = fmaxf(m, m2);
            float s1 = __expf(m  - M);
            float s2 = __expf(m2 - M);
            Z = Z * s1 + Z2 * s2;
            acc.x = acc.x * s1 + ax * s2;
            acc.y = acc.y * s1 + ay * s2;
            acc.z = acc.z * s1 + az * s2;
            acc.w = acc.w * s1 + aw * s2;
            m = M;
        }
        if (l == 0) { sm_m[w] = m; sm_z[w] = Z; }
        if (l < 8) {
            sm_acc[w * 32 + o4 * 4 + 0] = acc.x;
            sm_acc[w * 32 + o4 * 4 + 1] = acc.y;
            sm_acc[w * 32 + o4 * 4 + 2] = acc.z;
            sm_acc[w * 32 + o4 * 4 + 3] = acc.w;
        }
        __syncthreads();

        if (t < 32) {
            float M = sm_m[0];
#pragma unroll
            for (int g = 1; g < 16; g++) M = fmaxf(M, sm_m[g]);
            float Zt = 0.f, st = 0.f;
#pragma unroll
            for (int g = 0; g < 16; g++) {
                float f = __expf(sm_m[g] - M);
                Zt += sm_z[g] * f;
                st += sm_acc[g * 32 + t] * f;
            }
            float v = st / Zt;
            float sq = v * v;
#pragma unroll
            for (int off = 16; off; off >>= 1)
                sq += __shfl_xor_sync(~0u, sq, off);
            float o = v * (sqrtf(sq) / (1.f + sq));
            if (it == 0)
                sm_w[t] += o;               // iter-3 weight = out1 + out2
            else
                out[cb * O_DIM + t] = o;
        }
        __syncthreads();
    }

    if (t == 0)
        asm volatile("mbarrier.inval.shared.b64 [%0];" :: "r"(mb) : "memory");
}

// ---------------------------------------------------------------------------
extern "C" void kernel_launch(void* const* d_in, const int* in_sizes, int n_in,
                              void* d_out, int out_size) {
    const float* x = (const float*)d_in[0];
    const float* W = (const float*)d_in[1];
    if (n_in >= 2 && in_sizes[0] > in_sizes[1]) {  // defensive input ordering
        x = (const float*)d_in[1];
        W = (const float*)d_in[0];
    }

    // P 128KB + sred 8KB + sm_w/m/z/acc + mbar
    const int SMEM2 = (N_DIM * O_DIM + 512 * 4 + 32 + 16 + 16 + 16 * 32) * 4 + 16;
    cudaFuncSetAttribute(routing_fused,
                         cudaFuncAttributeMaxDynamicSharedMemorySize, SMEM2);

    priors_kernel<<<dim3(N_DIM / 8, C_DIM), 256>>>(x, W);
    routing_fused<<<CB, 512, SMEM2>>>((float*)d_out);
}